// round 16
// baseline (speedup 1.0000x reference)
#include <cuda_runtime.h>
#include <cuda_bf16.h>
#include <cstdint>
#include <cmath>

// ---------------- problem constants ----------------
constexpr int Bn  = 2;
constexpr int Sn  = 1024;
constexpr int Dn  = 512;
constexpr int Hn  = 8;
constexpr int HDn = 64;
constexpr int FFn = 2048;
constexpr int Ln  = 4;
constexpr int Mn  = Bn * Sn;   // 2048
constexpr int BHn = Bn * Hn;   // 16
constexpr long long WLL = 4LL * Dn * Dn + 2LL * FFn * Dn;

#define EPSf   1e-7f
#define MAXNf  (1.0f - 1e-3f)

// ---------------- scratch ----------------
__device__ float g_x   [Mn * Dn];
__device__ float g_u   [Mn * FFn];
__device__ float g_mid [Mn * Dn];
__device__ float g_qf  [Mn * Dn];
__device__ float g_kf  [Mn * Dn];
__device__ float g_bqkv[Ln * 3 * Dn];
__device__ float g_q2  [BHn * Sn];
__device__ float g_k2  [BHn * Sn];
__device__ float g_lm1 [BHn * Sn];
__device__ __nv_bfloat16 g_lvh[Mn * Dn];
__device__ __nv_bfloat16 g_lvl[Mn * Dn];
__device__ __nv_bfloat16 g_ahi[Mn * FFn];
__device__ __nv_bfloat16 g_alo[Mn * FFn];
__device__ __nv_bfloat16 g_Whi[4 * WLL + Dn * Dn];
__device__ __nv_bfloat16 g_Wlo[4 * WLL + Dn * Dn];

// ---------------- PTX helpers ----------------
static __device__ __forceinline__ uint32_t smem_u32(const void* p) {
    return (uint32_t)__cvta_generic_to_shared(p);
}
static __device__ __forceinline__ void cp16(uint32_t dst, const void* src) {
    asm volatile("cp.async.cg.shared.global [%0], [%1], 16;" :: "r"(dst), "l"(src));
}
static __device__ __forceinline__ void cp_commit() {
    asm volatile("cp.async.commit_group;" ::: "memory");
}
template<int N>
static __device__ __forceinline__ void cp_wait() {
    asm volatile("cp.async.wait_group %0;" :: "n"(N) : "memory");
}
static __device__ __forceinline__ void ldm4(uint32_t* r, uint32_t addr) {
    asm volatile("ldmatrix.sync.aligned.m8n8.x4.shared.b16 {%0,%1,%2,%3}, [%4];"
                 : "=r"(r[0]), "=r"(r[1]), "=r"(r[2]), "=r"(r[3]) : "r"(addr));
}
static __device__ __forceinline__ void ldm4t(uint32_t* r, uint32_t addr) {
    asm volatile("ldmatrix.sync.aligned.m8n8.x4.trans.shared.b16 {%0,%1,%2,%3}, [%4];"
                 : "=r"(r[0]), "=r"(r[1]), "=r"(r[2]), "=r"(r[3]) : "r"(addr));
}
static __device__ __forceinline__ void mma16816(float* d, const uint32_t* a, const uint32_t* b) {
    asm volatile("mma.sync.aligned.m16n8k16.row.col.f32.bf16.bf16.f32 "
                 "{%0,%1,%2,%3}, {%4,%5,%6,%7}, {%8,%9}, {%0,%1,%2,%3};"
                 : "+f"(d[0]), "+f"(d[1]), "+f"(d[2]), "+f"(d[3])
                 : "r"(a[0]), "r"(a[1]), "r"(a[2]), "r"(a[3]), "r"(b[0]), "r"(b[1]));
}
static __device__ __forceinline__ uint32_t f2tf(float x) {
    uint32_t r; asm("cvt.rna.tf32.f32 %0, %1;" : "=r"(r) : "f"(x)); return r;
}
static __device__ __forceinline__ void mma_tf32(float* d, const uint32_t* a, const uint32_t* b) {
    asm volatile("mma.sync.aligned.m16n8k8.row.col.f32.tf32.tf32.f32 "
                 "{%0,%1,%2,%3}, {%4,%5,%6,%7}, {%8,%9}, {%0,%1,%2,%3};"
                 : "+f"(d[0]), "+f"(d[1]), "+f"(d[2]), "+f"(d[3])
                 : "r"(a[0]), "r"(a[1]), "r"(a[2]), "r"(a[3]), "r"(b[0]), "r"(b[1]));
}

// ---------------- math helpers ----------------
static __device__ __forceinline__ float atanh_f(float x) {
    return 0.5f * (log1pf(x) - log1pf(-x));
}
template<int NT>
__device__ __forceinline__ float block_sum(float v) {
    __shared__ float sh[NT / 32];
#pragma unroll
    for (int o = 16; o > 0; o >>= 1) v += __shfl_xor_sync(0xffffffffu, v, o);
    int w = threadIdx.x >> 5;
    if ((threadIdx.x & 31) == 0) sh[w] = v;
    __syncthreads();
    float r = sh[0];
#pragma unroll
    for (int i = 1; i < NT / 32; i++) r += sh[i];
    __syncthreads();
    return r;
}
__device__ __forceinline__ float warp_sum(float v) {
#pragma unroll
    for (int o = 16; o > 0; o >>= 1) v += __shfl_xor_sync(0xffffffffu, v, o);
    return v;
}
__device__ __forceinline__ float group16_sum(float v) {
#pragma unroll
    for (int o = 8; o > 0; o >>= 1) v += __shfl_xor_sync(0xffffffffu, v, o);
    return v;
}
static __device__ __forceinline__ void store_split4(__nv_bfloat16* hi, __nv_bfloat16* lo,
                                                    size_t idx, float4 v) {
    __nv_bfloat16 h0 = __float2bfloat16(v.x), h1 = __float2bfloat16(v.y);
    __nv_bfloat16 h2 = __float2bfloat16(v.z), h3 = __float2bfloat16(v.w);
    __nv_bfloat16 l0 = __float2bfloat16(v.x - __bfloat162float(h0));
    __nv_bfloat16 l1 = __float2bfloat16(v.y - __bfloat162float(h1));
    __nv_bfloat16 l2 = __float2bfloat16(v.z - __bfloat162float(h2));
    __nv_bfloat16 l3 = __float2bfloat16(v.w - __bfloat162float(h3));
    ((__nv_bfloat162*)(hi + idx))[0] = __halves2bfloat162(h0, h1);
    ((__nv_bfloat162*)(hi + idx))[1] = __halves2bfloat162(h2, h3);
    ((__nv_bfloat162*)(lo + idx))[0] = __halves2bfloat162(l0, l1);
    ((__nv_bfloat162*)(lo + idx))[1] = __halves2bfloat162(l2, l3);
}

// ---------------- weight conversion ----------------
struct WCvtArgs {
    const float* src[25];
    long long    off[25];
    int          n4[25];
};
__global__ void k_wcvt(WCvtArgs a, __nv_bfloat16* __restrict__ hi, __nv_bfloat16* __restrict__ lo) {
    int t = blockIdx.y;
    int i = blockIdx.x * blockDim.x + threadIdx.x;
    if (i >= a.n4[t]) return;
    float4 v = ((const float4*)a.src[t])[i];
    store_split4(hi, lo, (size_t)a.off[t] + 4 * (size_t)i, v);
}
__global__ void k_bfill(const float* __restrict__ bq, const float* __restrict__ bk,
                        const float* __restrict__ bv, float* __restrict__ out) {
    int l = blockIdx.y;
    int i = blockIdx.x * blockDim.x + threadIdx.x;
    float v;
    if (i < Dn)            v = bq[l * Dn + i];
    else if (i < 2 * Dn)   v = bk[l * Dn + i - Dn];
    else                   v = bv[l * Dn + i - 2 * Dn];
    out[l * 3 * Dn + i] = v;
}

// ---------------- HMMA GEMM (3-pass split-bf16, 2-stage, 8 warps, 2 CTA/SM) ----------------
// RACE FIX: final iteration must fully drain cp.async groups (cp_wait<0>) because
// no new group is committed during the last two iterations; cp_wait<1> could leave
// the final K-chunk's own group pending while we read it.
constexpr int LDS = 72;
constexpr int STAGE_E = 4 * 64 * LDS;
constexpr int GEMM_SMEM = 2 * STAGE_E * 2;   // 73728 B

__global__ void __launch_bounds__(256, 2)
k_gemm_mma(const __nv_bfloat16* __restrict__ Ahi, const __nv_bfloat16* __restrict__ Alo,
           const __nv_bfloat16* __restrict__ Whi, const __nv_bfloat16* __restrict__ Wlo,
           const float* __restrict__ bias, float* __restrict__ C, int Ni, int Ki)
{
    extern __shared__ __nv_bfloat16 sm[];
    const int tid = threadIdx.x, wid = tid >> 5, lane = tid & 31;
    const int bm = blockIdx.y * 64, bn = blockIdx.x * 64;
    const int wm = (wid >> 1) * 16, wn = (wid & 1) * 32;
    const uint32_t sbase = smem_u32(sm);

    float acc[4][4];
#pragma unroll
    for (int b = 0; b < 4; b++)
#pragma unroll
        for (int c = 0; c < 4; c++) acc[b][c] = 0.f;

    const int NC = Ki >> 6;

    auto load_stage = [&](int c) {
        const uint32_t sb = sbase + (uint32_t)(c & 1) * STAGE_E * 2;
        const size_t k0 = (size_t)c * 64;
#pragma unroll
        for (int i = tid; i < 512; i += 256) {
            int row = i >> 3, seg = i & 7;
            const size_t gA = (size_t)(bm + row) * Ki + k0 + seg * 8;
            const size_t gB = (size_t)(bn + row) * Ki + k0 + seg * 8;
            uint32_t ro = (uint32_t)(row * LDS + seg * 8) * 2;
            cp16(sb + ro,                 Ahi + gA);
            cp16(sb + 64 * LDS * 2 + ro,  Alo + gA);
            cp16(sb + 128 * LDS * 2 + ro, Whi + gB);
            cp16(sb + 192 * LDS * 2 + ro, Wlo + gB);
        }
        cp_commit();
    };

    uint32_t ah[2][4], al[2][4], bh[2][4][2], bl[2][4][2];
    auto ldfrag = [&](uint32_t sb, int kk, int bf) {
        uint32_t koff = (uint32_t)(kk * 16) * 2 + (lane >> 4) * 16;
        uint32_t rA = (uint32_t)(wm + (lane & 15));
        ldm4(ah[bf], sb + rA * (LDS * 2) + koff);
        ldm4(al[bf], sb + (64 + rA) * (LDS * 2) + koff);
#pragma unroll
        for (int nt2 = 0; nt2 < 2; nt2++) {
            uint32_t rB = (uint32_t)(128 + wn + nt2 * 16 + (lane & 15));
            uint32_t t[4];
            ldm4(t, sb + rB * (LDS * 2) + koff);
            bh[bf][nt2 * 2][0] = t[0]; bh[bf][nt2 * 2 + 1][0] = t[1];
            bh[bf][nt2 * 2][1] = t[2]; bh[bf][nt2 * 2 + 1][1] = t[3];
            ldm4(t, sb + (64 + rB) * (LDS * 2) + koff);
            bl[bf][nt2 * 2][0] = t[0]; bl[bf][nt2 * 2 + 1][0] = t[1];
            bl[bf][nt2 * 2][1] = t[2]; bl[bf][nt2 * 2 + 1][1] = t[3];
        }
    };

    load_stage(0);
    if (NC > 1) load_stage(1);

    for (int c = 0; c < NC; c++) {
        const uint32_t sb = sbase + (uint32_t)(c & 1) * STAGE_E * 2;
        if (c + 1 < NC) cp_wait<1>();
        else            cp_wait<0>();   // RACE FIX: drain the final group before reading it
        __syncthreads();

        ldfrag(sb, 0, 0);
#pragma unroll
        for (int kk = 0; kk < 4; kk++) {
            const int cur = kk & 1, nxt = cur ^ 1;
            if (kk < 3) ldfrag(sb, kk + 1, nxt);
#pragma unroll
            for (int nt = 0; nt < 4; nt++)
                mma16816(acc[nt], ah[cur], bh[cur][nt]);
#pragma unroll
            for (int nt = 0; nt < 4; nt++)
                mma16816(acc[nt], ah[cur], bl[cur][nt]);
#pragma unroll
            for (int nt = 0; nt < 4; nt++)
                mma16816(acc[nt], al[cur], bh[cur][nt]);
        }
        __syncthreads();
        if (c + 2 < NC) load_stage(c + 2);
    }

    {
        int r0 = bm + wm + (lane >> 2);
#pragma unroll
        for (int nt = 0; nt < 4; nt++) {
            int col = bn + wn + nt * 8 + 2 * (lane & 3);
            float b0 = bias[col], b1 = bias[col + 1];
            float2 v0 = make_float2(acc[nt][0] + b0, acc[nt][1] + b1);
            float2 v1 = make_float2(acc[nt][2] + b0, acc[nt][3] + b1);
            *(float2*)(C + (size_t)r0 * Ni + col) = v0;
            *(float2*)(C + (size_t)(r0 + 8) * Ni + col) = v1;
        }
    }
}

// ---------------- fused elementwise kernels (block versions, frozen) ----------------

template<int NT>
__global__ void k_mobius_add(const float* __restrict__ x, const float* __restrict__ y,
                             float* __restrict__ out, int ymod) {
    constexpr int P = Dn / NT;
    int r = blockIdx.x;
    const float* xr = x + (size_t)r * Dn;
    const float* yr = y + (size_t)(r % ymod) * Dn;
    float xl[P], yl[P];
    float x2 = 0.f, y2 = 0.f, xy = 0.f;
#pragma unroll
    for (int i = 0; i < P; i++) {
        int j = threadIdx.x + i * NT;
        xl[i] = xr[j]; yl[i] = yr[j];
        x2 += xl[i] * xl[i]; y2 += yl[i] * yl[i]; xy += xl[i] * yl[i];
    }
    x2 = block_sum<NT>(x2);
    y2 = block_sum<NT>(y2);
    xy = block_sum<NT>(xy);
    float den = fmaxf(1.f + 2.f * xy + x2 * y2, EPSf);
    float ca = (1.f + 2.f * xy + y2) / den;
    float cb = (1.f - x2) / den;
    float zl[P]; float n2 = 0.f;
#pragma unroll
    for (int i = 0; i < P; i++) { zl[i] = ca * xl[i] + cb * yl[i]; n2 += zl[i] * zl[i]; }
    n2 = block_sum<NT>(n2);
    float n = sqrtf(fmaxf(n2, EPSf * EPSf));
    float sc = fminf(1.f, MAXNf / n);
#pragma unroll
    for (int i = 0; i < P; i++) out[(size_t)r * Dn + threadIdx.x + i * NT] = zl[i] * sc;
}

__global__ void __launch_bounds__(128)
k_pln2bf(const float* __restrict__ x, const float* __restrict__ w, const float* __restrict__ b,
         __nv_bfloat16* __restrict__ hi, __nv_bfloat16* __restrict__ lo) {
    int r = blockIdx.x, tid = threadIdx.x;
    const float* xr = x + (size_t)r * Dn;
    float4 xv = *(const float4*)(xr + tid * 4);
    float ss = xv.x * xv.x + xv.y * xv.y + xv.z * xv.z + xv.w * xv.w;
    ss = block_sum<128>(ss);
    float n  = sqrtf(fmaxf(ss, EPSf * EPSf));
    float nc = fminf(fmaxf(n, EPSf), MAXNf);
    float ls = atanh_f(nc) / nc;
    float4 tl = make_float4(ls * xv.x, ls * xv.y, ls * xv.z, ls * xv.w);
    float st = tl.x + tl.y + tl.z + tl.w;
    st = block_sum<128>(st);
    float mu = st / (float)Dn;
    float d0 = tl.x - mu, d1 = tl.y - mu, d2 = tl.z - mu, d3 = tl.w - mu;
    float sv = d0 * d0 + d1 * d1 + d2 * d2 + d3 * d3;
    sv = block_sum<128>(sv);
    float inv = rsqrtf(sv / (float)Dn + 1e-5f);
    float4 wv = *(const float4*)(w + tid * 4);
    float4 bv = *(const float4*)(b + tid * 4);
    float4 yv = make_float4(d0 * inv * wv.x + bv.x, d1 * inv * wv.y + bv.y,
                            d2 * inv * wv.z + bv.z, d3 * inv * wv.w + bv.w);
    float sy = yv.x * yv.x + yv.y * yv.y + yv.z * yv.z + yv.w * yv.w;
    sy = block_sum<128>(sy);
    float ny = sqrtf(fmaxf(sy, EPSf * EPSf));
    float es = tanhf(ny) / ny;
    float tb = tanhf(ny);
    float cb = fminf(fmaxf(tb, EPSf), MAXNf);
    float s2 = atanh_f(cb) / cb;
    float sc = es * s2;
    store_split4(hi, lo, (size_t)r * Dn + tid * 4,
                 make_float4(sc * yv.x, sc * yv.y, sc * yv.z, sc * yv.w));
}

// fused: x = project(mobius_add(x, expmap0(g))); then pln(x) -> logmap0 -> bf16 hi/lo
__global__ void __launch_bounds__(128)
k_expmadd_pln(const float* __restrict__ g, float* __restrict__ x,
              const float* __restrict__ w, const float* __restrict__ b,
              __nv_bfloat16* __restrict__ hi, __nv_bfloat16* __restrict__ lo) {
    int r = blockIdx.x, tid = threadIdx.x;
    float4 gv = *(const float4*)(g + (size_t)r * Dn + tid * 4);
    float4 xv = *(const float4*)(x + (size_t)r * Dn + tid * 4);
    float lg = gv.x * gv.x + gv.y * gv.y + gv.z * gv.z + gv.w * gv.w;
    float lx = xv.x * xv.x + xv.y * xv.y + xv.z * xv.z + xv.w * xv.w;
    float lxg = xv.x * gv.x + xv.y * gv.y + xv.z * gv.z + xv.w * gv.w;
    float g2 = block_sum<128>(lg);
    float x2 = block_sum<128>(lx);
    float xg = block_sum<128>(lxg);
    float ng = sqrtf(fmaxf(g2, EPSf * EPSf));
    float s  = tanhf(ng) / ng;
    float y2 = s * s * g2;
    float xy = s * xg;
    float den = fmaxf(1.f + 2.f * xy + x2 * y2, EPSf);
    float ca = (1.f + 2.f * xy + y2) / den;
    float cb2 = (1.f - x2) / den * s;
    float4 zv = make_float4(ca * xv.x + cb2 * gv.x, ca * xv.y + cb2 * gv.y,
                            ca * xv.z + cb2 * gv.z, ca * xv.w + cb2 * gv.w);
    float n2 = zv.x * zv.x + zv.y * zv.y + zv.z * zv.z + zv.w * zv.w;
    n2 = block_sum<128>(n2);
    float n = sqrtf(fmaxf(n2, EPSf * EPSf));
    float scp = fminf(1.f, MAXNf / n);
    float4 nx = make_float4(scp * zv.x, scp * zv.y, scp * zv.z, scp * zv.w);
    *(float4*)(x + (size_t)r * Dn + tid * 4) = nx;

    float ss = scp * scp * n2;
    float n1  = sqrtf(fmaxf(ss, EPSf * EPSf));
    float nc1 = fminf(fmaxf(n1, EPSf), MAXNf);
    float ls = atanh_f(nc1) / nc1;
    float4 tl = make_float4(ls * nx.x, ls * nx.y, ls * nx.z, ls * nx.w);
    float st = tl.x + tl.y + tl.z + tl.w;
    st = block_sum<128>(st);
    float mu = st / (float)Dn;
    float d0 = tl.x - mu, d1 = tl.y - mu, d2 = tl.z - mu, d3 = tl.w - mu;
    float sv = d0 * d0 + d1 * d1 + d2 * d2 + d3 * d3;
    sv = block_sum<128>(sv);
    float inv = rsqrtf(sv / (float)Dn + 1e-5f);
    float4 wv = *(const float4*)(w + tid * 4);
    float4 bv = *(const float4*)(b + tid * 4);
    float4 yv = make_float4(d0 * inv * wv.x + bv.x, d1 * inv * wv.y + bv.y,
                            d2 * inv * wv.z + bv.z, d3 * inv * wv.w + bv.w);
    float sy = yv.x * yv.x + yv.y * yv.y + yv.z * yv.z + yv.w * yv.w;
    sy = block_sum<128>(sy);
    float ny = sqrtf(fmaxf(sy, EPSf * EPSf));
    float es = tanhf(ny) / ny;
    float tb = tanhf(ny);
    float cb3 = fminf(fmaxf(tb, EPSf), MAXNf);
    float s2 = atanh_f(cb3) / cb3;
    float sc = es * s2;
    store_split4(hi, lo, (size_t)r * Dn + tid * 4,
                 make_float4(sc * yv.x, sc * yv.y, sc * yv.z, sc * yv.w));
}

// final-layer: x' = project(mobius_add(x, expmap0(g))); logmap0(x') -> bf16 hi/lo
__global__ void __launch_bounds__(128)
k_expmadd_log2bf(const float* __restrict__ g, const float* __restrict__ x,
                 __nv_bfloat16* __restrict__ hi, __nv_bfloat16* __restrict__ lo) {
    int r = blockIdx.x, tid = threadIdx.x;
    float4 gv = *(const float4*)(g + (size_t)r * Dn + tid * 4);
    float4 xv = *(const float4*)(x + (size_t)r * Dn + tid * 4);
    float lg = gv.x * gv.x + gv.y * gv.y + gv.z * gv.z + gv.w * gv.w;
    float lx = xv.x * xv.x + xv.y * xv.y + xv.z * xv.z + xv.w * xv.w;
    float lxg = xv.x * gv.x + xv.y * gv.y + xv.z * gv.z + xv.w * gv.w;
    float g2 = block_sum<128>(lg);
    float x2 = block_sum<128>(lx);
    float xg = block_sum<128>(lxg);
    float ng = sqrtf(fmaxf(g2, EPSf * EPSf));
    float s  = tanhf(ng) / ng;
    float y2 = s * s * g2;
    float xy = s * xg;
    float den = fmaxf(1.f + 2.f * xy + x2 * y2, EPSf);
    float ca = (1.f + 2.f * xy + y2) / den;
    float cb2 = (1.f - x2) / den * s;
    float4 zv = make_float4(ca * xv.x + cb2 * gv.x, ca * xv.y + cb2 * gv.y,
                            ca * xv.z + cb2 * gv.z, ca * xv.w + cb2 * gv.w);
    float n2 = zv.x * zv.x + zv.y * zv.y + zv.z * zv.z + zv.w * zv.w;
    n2 = block_sum<128>(n2);
    float n = sqrtf(fmaxf(n2, EPSf * EPSf));
    float scp = fminf(1.f, MAXNf / n);
    float ss = scp * scp * n2;
    float n1  = sqrtf(fmaxf(ss, EPSf * EPSf));
    float nc1 = fminf(fmaxf(n1, EPSf), MAXNf);
    float ls = atanh_f(nc1) / nc1;
    float sc = ls * scp;
    store_split4(hi, lo, (size_t)r * Dn + tid * 4,
                 make_float4(sc * zv.x, sc * zv.y, sc * zv.z, sc * zv.w));
}

// fused-QKV post: Q/K -> fp32 (+q2/k2), V -> lamv bf16 hi/lo (+lm1)
__global__ void __launch_bounds__(128)
k_post_qkv3(const float* __restrict__ u,
            float* __restrict__ qf, float* __restrict__ kf,
            __nv_bfloat16* __restrict__ lvh, __nv_bfloat16* __restrict__ lvl,
            float* __restrict__ q2g, float* __restrict__ k2g, float* __restrict__ lmg,
            float ratio) {
    int which = blockIdx.y;
    int r = blockIdx.x, tid = threadIdx.x;
    int b = r / Sn, s = r % Sn;
    float4 uv = *(const float4*)(u + (size_t)r * (3 * Dn) + which * Dn + tid * 4);
    float ss = uv.x * uv.x + uv.y * uv.y + uv.z * uv.z + uv.w * uv.w;
    float bs = block_sum<128>(ss);
    float n  = sqrtf(fmaxf(bs, EPSf * EPSf));
    float s1 = tanhf(n) / n;
    float t  = tanhf(n);
    float c  = fminf(fmaxf(t, EPSf), MAXNf);
    float s2 = atanh_f(c) / c;
    float sc = s1 * s2 * ratio;
    float4 th = make_float4(sc * uv.x, sc * uv.y, sc * uv.z, sc * uv.w);
    float hs = sc * sc * ss;
    hs = group16_sum(hs);
    float nh = sqrtf(fmaxf(hs, EPSf * EPSf));
    float es = tanhf(nh) / nh;
    int h = tid >> 4;
    size_t row = (size_t)(b * Hn + h) * Sn + s;
    size_t dst = row * HDn + (tid & 15) * 4;
    if (which == 0) {
        *(float4*)(qf + dst) = make_float4(es * th.x, es * th.y, es * th.z, es * th.w);
        if ((tid & 15) == 0) q2g[row] = es * es * hs;
    } else if (which == 1) {
        *(float4*)(kf + dst) = make_float4(es * th.x, es * th.y, es * th.z, es * th.w);
        if ((tid & 15) == 0) k2g[row] = es * es * hs;
    } else {
        float vsq = es * es * hs;
        float lam = 2.f / fmaxf(1.f - vsq, EPSf);
        float ls2 = lam * es;
        store_split4(lvh, lvl, dst, make_float4(ls2 * th.x, ls2 * th.y, ls2 * th.z, ls2 * th.w));
        if ((tid & 15) == 0) lmg[row] = lam - 1.f;
    }
}

// ---------------- fused attention: 3xTF32 HMMA QK + MUFU transform + HMMA PV ----------------
// (Round-10 version, frozen)
constexpr int ALD = 72;
constexpr int O_QS  = 0;
constexpr int O_KS  = 17408;
constexpr int O_LVH = 34816;
constexpr int O_LVL = 44032;
constexpr int O_PHI = 53248;
constexpr int O_PLO = 62464;
constexpr int O_Q2  = 71680;
constexpr int O_K2  = 71936;
constexpr int O_LMS = 72192;
constexpr int O_RS  = 72448;
constexpr int O_DS  = 72960;
constexpr int O_INV = 73472;
constexpr int ATT2_SMEM = 73728;

__global__ void __launch_bounds__(256)
k_attn3(const float* __restrict__ qf, const float* __restrict__ kf,
        const __nv_bfloat16* __restrict__ lvh, const __nv_bfloat16* __restrict__ lvl,
        const float* __restrict__ q2g, const float* __restrict__ k2g,
        const float* __restrict__ lmg,
        const float* __restrict__ tau, const float* __restrict__ gam, int l,
        float* __restrict__ mid)
{
    extern __shared__ char smb[];
    float* smf = (float*)smb;
    const uint32_t sb = smem_u32(smb);
    const int tid = threadIdx.x, wid = tid >> 5, lane = tid & 31;
    const int gid = lane >> 2, tig = lane & 3;
    const int bh = blockIdx.y;
    const int wm = (wid >> 1) * 16, wn = (wid & 1) * 32;
    const float tv = tau[l], gv = gam[l];

    for (int p = 0; p < 2; p++) {
        const int it = p ? (15 - (int)blockIdx.x) : (int)blockIdx.x;

        {
            const float* Q = qf + ((size_t)bh * Sn + it * 64) * HDn;
#pragma unroll
            for (int f = tid; f < 1024; f += 256) {
                int row = f >> 4, c = (f & 15) * 4;
                *(float4*)&smf[row * 68 + c] = *(const float4*)(Q + row * HDn + c);
            }
            if (tid < 64) smf[O_Q2 / 4 + tid] = q2g[(size_t)bh * Sn + it * 64 + tid];
        }
        float acc2[4][4];
#pragma unroll
        for (int a = 0; a < 4; a++)
#pragma unroll
            for (int c = 0; c < 4; c++) acc2[a][c] = 0.f;
        float rs_t[2] = {0.f, 0.f};
        float ds_t[2] = {0.f, 0.f};
        __syncthreads();

        for (int jt = 0; jt <= it; jt++) {
            {
                const float* K = kf + ((size_t)bh * Sn + jt * 64) * HDn;
#pragma unroll
                for (int f = tid; f < 1024; f += 256) {
                    int row = f >> 4, c = (f & 15) * 4;
                    *(float4*)&smf[O_KS / 4 + row * 68 + c] = *(const float4*)(K + row * HDn + c);
                }
                const size_t rb = ((size_t)bh * Sn + jt * 64) * HDn;
#pragma unroll
                for (int i = tid; i < 512; i += 256) {
                    int row = i >> 3, seg = i & 7;
                    uint32_t ro = (uint32_t)(row * ALD + seg * 8) * 2;
                    cp16(sb + O_LVH + ro, lvh + rb + row * HDn + seg * 8);
                    cp16(sb + O_LVL + ro, lvl + rb + row * HDn + seg * 8);
                }
                cp_commit();
                if (tid < 64) {
                    smf[O_K2 / 4 + tid]  = k2g[(size_t)bh * Sn + jt * 64 + tid];
                    smf[O_LMS / 4 + tid] = lmg[(size_t)bh * Sn + jt * 64 + tid];
                }
            }
            cp_wait<0>();
            __syncthreads();

            float sacc[4][4];
#pragma unroll
            for (int a = 0; a < 4; a++)
#pragma unroll
                for (int c = 0; c < 4; c++) sacc[a][c] = 0.f;
#pragma unroll
            for (int kc = 0; kc < 8; kc++) {
                const int d0 = kc * 8 + tig;
                float a0 = smf[(wm + gid) * 68 + d0];
                float a1 = smf[(wm + gid + 8) * 68 + d0];
                float a2 = smf[(wm + gid) * 68 + d0 + 4];
                float a3 = smf[(wm + gid + 8) * 68 + d0 + 4];
                uint32_t ah[4] = {f2tf(a0), f2tf(a1), f2tf(a2), f2tf(a3)};
                uint32_t al[4] = {f2tf(a0 - __uint_as_float(ah[0])),
                                  f2tf(a1 - __uint_as_float(ah[1])),
                                  f2tf(a2 - __uint_as_float(ah[2])),
                                  f2tf(a3 - __uint_as_float(ah[3]))};
                uint32_t bhv[4][2], blv[4][2];
#pragma unroll
                for (int nt = 0; nt < 4; nt++) {
                    float b0 = smf[O_KS / 4 + (wn + nt * 8 + gid) * 68 + d0];
                    float b1 = smf[O_KS / 4 + (wn + nt * 8 + gid) * 68 + d0 + 4];
                    bhv[nt][0] = f2tf(b0); bhv[nt][1] = f2tf(b1);
                    blv[nt][0] = f2tf(b0 - __uint_as_float(bhv[nt][0]));
                    blv[nt][1] = f2tf(b1 - __uint_as_float(bhv[nt][1]));
                }
#pragma unroll
                for (int nt = 0; nt < 4; nt++) mma_tf32(sacc[nt], ah, bhv[nt]);
#pragma unroll
                for (int nt = 0; nt < 4; nt++) mma_tf32(sacc[nt], ah, blv[nt]);
#pragma unroll
                for (int nt = 0; nt < 4; nt++) mma_tf32(sacc[nt], al, bhv[nt]);
            }

            const bool diag = (jt == it);
            {
                const int r0 = wm + gid;
                float qq0 = smf[O_Q2 / 4 + r0], qq1 = smf[O_Q2 / 4 + r0 + 8];
                float di0 = 1.f - qq0, di1 = 1.f - qq1;
#pragma unroll
                for (int nt = 0; nt < 4; nt++) {
                    int c0 = wn + nt * 8 + 2 * tig;
                    float kk0 = smf[O_K2 / 4 + c0],  kk1 = smf[O_K2 / 4 + c0 + 1];
                    float lm0 = smf[O_LMS / 4 + c0], lm1v = smf[O_LMS / 4 + c0 + 1];
                    float dj0 = 1.f - kk0, dj1 = 1.f - kk1;
                    float e[4];
#pragma unroll
                    for (int z = 0; z < 4; z++) {
                        float qq = (z < 2) ? qq0 : qq1;
                        float di = (z < 2) ? di0 : di1;
                        float kk2 = (z & 1) ? kk1 : kk0;
                        float dj = (z & 1) ? dj1 : dj0;
                        float d2 = fmaxf(qq + kk2 - 2.f * sacc[nt][z], 0.f);
                        float dn = fmaxf(di * dj, EPSf);
                        float uu = fmaxf(__fdividef(2.f * d2, dn), 1.1920929e-7f);
                        float ar = uu * (uu + 2.f);
                        float w = 1.f + uu + ar * rsqrtf(ar);
                        e[z] = __expf(fmaf(-tv, __logf(w), -gv));
                    }
                    if (diag) {
                        if (c0 > r0)         e[0] = 0.f;
                        if (c0 + 1 > r0)     e[1] = 0.f;
                        if (c0 > r0 + 8)     e[2] = 0.f;
                        if (c0 + 1 > r0 + 8) e[3] = 0.f;
                    }
                    rs_t[0] += e[0] + e[1];
                    ds_t[0] += e[0] * lm0 + e[1] * lm1v;
                    rs_t[1] += e[2] + e[3];
                    ds_t[1] += e[2] * lm0 + e[3] * lm1v;
                    __nv_bfloat16 h00 = __float2bfloat16(e[0]), h01 = __float2bfloat16(e[1]);
                    __nv_bfloat16 h10 = __float2bfloat16(e[2]), h11 = __float2bfloat16(e[3]);
                    *(__nv_bfloat162*)(smb + O_PHI + (r0 * ALD + c0) * 2) = __halves2bfloat162(h00, h01);
                    *(__nv_bfloat162*)(smb + O_PHI + ((r0 + 8) * ALD + c0) * 2) = __halves2bfloat162(h10, h11);
                    *(__nv_bfloat162*)(smb + O_PLO + (r0 * ALD + c0) * 2) = __halves2bfloat162(
                        __float2bfloat16(e[0] - __bfloat162float(h00)),
                        __float2bfloat16(e[1] - __bfloat162float(h01)));
                    *(__nv_bfloat162*)(smb + O_PLO + ((r0 + 8) * ALD + c0) * 2) = __halves2bfloat162(
                        __float2bfloat16(e[2] - __bfloat162float(h10)),
                        __float2bfloat16(e[3] - __bfloat162float(h11)));
                }
            }
            __syncthreads();

#pragma unroll
            for (int kk = 0; kk < 4; kk++) {
                uint32_t koff = (uint32_t)(kk * 16) * 2 + (lane >> 4) * 16;
                uint32_t ph[4], pl[4], vh_[4][2], vl_[4][2];
                uint32_t rA = (uint32_t)(wm + (lane & 15));
                ldm4(ph, sb + O_PHI + rA * (ALD * 2) + koff);
                ldm4(pl, sb + O_PLO + rA * (ALD * 2) + koff);
#pragma unroll
                for (int q = 0; q < 2; q++) {
                    uint32_t row = (uint32_t)(kk * 16 + (lane & 15));
                    uint32_t col = (uint32_t)(wn + q * 16 + ((lane >> 4) << 3));
                    uint32_t t[4];
                    ldm4t(t, sb + O_LVH + (row * ALD + col) * 2);
                    vh_[q * 2][0] = t[0]; vh_[q * 2][1] = t[1];
                    vh_[q * 2 + 1][0] = t[2]; vh_[q * 2 + 1][1] = t[3];
                    ldm4t(t, sb + O_LVL + (row * ALD + col) * 2);
                    vl_[q * 2][0] = t[0]; vl_[q * 2][1] = t[1];
                    vl_[q * 2 + 1][0] = t[2]; vl_[q * 2 + 1][1] = t[3];
                }
#pragma unroll
                for (int nt = 0; nt < 4; nt++) mma16816(acc2[nt], ph, vh_[nt]);
#pragma unroll
                for (int nt = 0; nt < 4; nt++) mma16816(acc2[nt], ph, vl_[nt]);
#pragma unroll
                for (int nt = 0; nt < 4; nt++) mma16816(acc2[nt], pl, vh_[nt]);
            }
            __syncthreads();
        }

#pragma unroll
        for (int hf = 0; hf < 2; hf++) {
            float v = rs_t[hf];
            v += __shfl_xor_sync(0xffffffffu, v, 1);
            v += __shfl_xor_sync(0xffffffffu, v, 2);
            float w = ds_t[hf];
            w += __shfl_xor_sync(0xffffffffu, w, 1);
            w += __shfl_xor_sync(0xffffffffu, w, 2);
            if (tig == 0) {
                int r = wm + hf * 8 + gid;
                int half = (wid & 1) * 64;
                smf[O_RS / 4 + half + r] = v;
                smf[O_DS / 4 + half + r] = w;
            }
        }
        __syncthreads();
        if (tid < 64) {
            float rst = smf[O_RS / 4 + tid] + smf[O_RS / 4 + 64 + tid];
            float dst = smf[O_DS / 4 + tid] + smf[O_DS / 4 + 64 + tid];
            smf[O_INV / 4 + tid] = __fdividef(1.f, fmaxf(dst, EPSf * rst));
        }
        __syncthreads();

        {
            int r0 = wm + gid;
            float i0 = smf[O_INV / 4 + r0], i1 = smf[O_INV / 4 + r0 + 8];
#pragma unroll
            for (int nt = 0; nt < 4; nt++) {
                int c0 = wn + nt * 8 + 2 * tig;
                smf[O_KS / 4 + r0 * 68 + c0]           = acc2[nt][0] * i0;
                smf[O_KS / 4 + r0 * 68 + c0 + 1]       = acc2[nt][1] * i0;
                smf[O_KS / 4 + (r0 + 8) * 68 + c0]     = acc2[nt][2] * i1;
                smf[O_KS / 4 + (r0 + 8) * 68 + c0 + 1] = acc2[nt][3] * i1;
            }
        }
        __syncthreads();

        {
            int r = tid >> 2, cg = (tid & 3) * 16;
            const float* nr = smf + O_KS / 4 + r * 68 + cg;
            float ss2 = 0.f;
#pragma unroll
            for (int c = 0; c < 16; c++) { float m = nr[c]; ss2 += m * m; }
            ss2 += __shfl_xor_sync(0xffffffffu, ss2, 1);
            ss2 += __shfl_xor_sync(0xffffffffu, ss2, 2);
            float n  = sqrtf(fmaxf(ss2, EPSf * EPSf));
            float nc = fminf(fmaxf(n, EPSf), MAXNf);
            float tt = tanhf(0.5f * atanh_f(nc));
            float s1 = tt / nc;
            float ny = sqrtf(fmaxf(s1 * s1 * ss2, EPSf * EPSf));
            float s2 = fminf(1.f, MAXNf / ny);
            float sc = s1 * s2;
            float* dst = mid + ((size_t)bh * Sn + it * 64 + r) * HDn + cg;
#pragma unroll
            for (int c = 0; c < 16; c += 4)
                *(float4*)(dst + c) = make_float4(sc * nr[c], sc * nr[c + 1],
                                                  sc * nr[c + 2], sc * nr[c + 3]);
        }
        __syncthreads();
    }
}

// concat heads -> expmap0 -> logmap0 -> bf16 hi/lo (block version, frozen)
__global__ void __launch_bounds__(128)
k_concat2bf(const float* __restrict__ mh, __nv_bfloat16* __restrict__ hi,
            __nv_bfloat16* __restrict__ lo, float ratio) {
    int r = blockIdx.x, tid = threadIdx.x;
    int b = r / Sn, s = r % Sn;
    __shared__ float row[Dn];
    int warp = tid >> 5, lane = tid & 31;
#pragma unroll
    for (int hh = 0; hh < 2; hh++) {
        int h = warp * 2 + hh;
        const float* src = mh + ((size_t)((b * Hn + h) * Sn + s)) * HDn;
        float v0 = src[lane], v1 = src[lane + 32];
        float ss = warp_sum(v0 * v0 + v1 * v1);
        float n  = sqrtf(fmaxf(ss, EPSf * EPSf));
        float nc = fminf(fmaxf(n, EPSf), MAXNf);
        float sc = atanh_f(nc) / nc * ratio;
        row[h * HDn + lane]      = sc * v0;
        row[h * HDn + lane + 32] = sc * v1;
    }
    __syncthreads();
    float4 vl = *(const float4*)&row[tid * 4];
    float ss = vl.x * vl.x + vl.y * vl.y + vl.z * vl.z + vl.w * vl.w;
    ss = block_sum<128>(ss);
    float n  = sqrtf(fmaxf(ss, EPSf * EPSf));
    float es = tanhf(n) / n;
    float tb = tanhf(n);
    float cb = fminf(fmaxf(tb, EPSf), MAXNf);
    float s2 = atanh_f(cb) / cb;
    float sc = es * s2;
    store_split4(hi, lo, (size_t)r * Dn + tid * 4,
                 make_float4(sc * vl.x, sc * vl.y, sc * vl.z, sc * vl.w));
}

__global__ void __launch_bounds__(256)
k_ffnmid2bf(const float* __restrict__ u, __nv_bfloat16* __restrict__ hi,
            __nv_bfloat16* __restrict__ lo) {
    int r = blockIdx.x, tid = threadIdx.x;
    const float* ur = u + (size_t)r * FFn;
    float4 u0 = *(const float4*)(ur + tid * 4);
    float4 u1 = *(const float4*)(ur + 1024 + tid * 4);
    float ss = u0.x * u0.x + u0.y * u0.y + u0.z * u0.z + u0.w * u0.w
             + u1.x * u1.x + u1.y * u1.y + u1.z * u1.z + u1.w * u1.w;
    ss = block_sum<256>(ss);
    float n0 = sqrtf(fmaxf(ss, EPSf * EPSf));
    float t0 = tanhf(n0);
    float s1 = t0 / n0;
    float c0 = fminf(fmaxf(t0, EPSf), MAXNf);
    float a0 = atanh_f(c0) / c0;
    float w  = a0 * s1;
    float4 r0 = make_float4(fmaxf(w * u0.x, 0.f), fmaxf(w * u0.y, 0.f),
                            fmaxf(w * u0.z, 0.f), fmaxf(w * u0.w, 0.f));
    float4 r1 = make_float4(fmaxf(w * u1.x, 0.f), fmaxf(w * u1.y, 0.f),
                            fmaxf(w * u1.z, 0.f), fmaxf(w * u1.w, 0.f));
    float st = r0.x * r0.x + r0.y * r0.y + r0.z * r0.z + r0.w * r0.w
             + r1.x * r1.x + r1.y * r1.y + r1.z * r1.z + r1.w * r1.w;
    st = block_sum<256>(st);
    float n1 = sqrtf(fmaxf(st, EPSf * EPSf));
    float e1 = tanhf(n1) / n1;
    float t1 = tanhf(n1);
    float c1 = fminf(fmaxf(t1, EPSf), MAXNf);
    float a1 = atanh_f(c1) / c1;
    float sc = a1 * e1;
    store_split4(hi, lo, (size_t)r * FFn + tid * 4,
                 make_float4(sc * r0.x, sc * r0.y, sc * r0.z, sc * r0.w));
    store_split4(hi, lo, (size_t)r * FFn + 1024 + tid * 4,
                 make_float4(sc * r1.x, sc * r1.y, sc * r1.z, sc * r1.w));
}

__global__ void __launch_bounds__(128)
k_expmap_out(const float* __restrict__ x, float* __restrict__ out) {
    int r = blockIdx.x, tid = threadIdx.x;
    float4 xv = *(const float4*)(x + (size_t)r * Dn + tid * 4);
    float ss = xv.x * xv.x + xv.y * xv.y + xv.z * xv.z + xv.w * xv.w;
    ss = block_sum<128>(ss);
    float n = sqrtf(fmaxf(ss, EPSf * EPSf));
    float s = tanhf(n) / n;
    *(float4*)(out + (size_t)r * Dn + tid * 4) =
        make_float4(s * xv.x, s * xv.y, s * xv.z, s * xv.w);
}

// ---------------- host orchestration ----------------
extern "C" void kernel_launch(void* const* d_in, const int* in_sizes, int n_in,
                              void* d_out, int out_size) {
    (void)in_sizes; (void)n_in; (void)out_size;
    const float* x    = (const float*)d_in[0];
    const float* pos  = (const float*)d_in[1];
    const float* ln1w = (const float*)d_in[2];
    const float* ln1b = (const float*)d_in[3];
    const float* ln2w = (const float*)d_in[4];
    const float* ln2b = (const float*)d_in[5];
    const float* Wq   = (const float*)d_in[6];
    const float* bq   = (const float*)d_in[7];
    const float* Wk   = (const float*)d_in[8];
    const float* bk   = (const float*)d_in[9];
    const float* Wv   = (const float*)d_in[10];
    const float* bv   = (const float*)d_in[11];
    const float* Wo   = (const float*)d_in[12];
    const float* bo   = (const float*)d_in[13];
    const float* W1   = (const float*)d_in[14];
    const float* b1   = (const float*)d_in[15];
    const float* W2   = (const float*)d_in[16];
    const float* b2   = (const float*)d_in[17];
    const float* tau  = (const float*)d_in[18];
    const float* gam  = (const float*)d_in[19];
    const float* Wout = (const float*)d_in[20];
    const float* bout = (const float*)d_in[21];
    float* outp = (float*)d_out;

    float *px, *pu, *pm, *pqf, *pkf, *pbq, *pq2, *pk2, *plm;
    __nv_bfloat16 *pahi, *palo, *pwhi, *pwlo, *plh, *pll;
    cudaGetSymbolAddress((void**)&px,  g_x);
    cudaGetSymbolAddress((void**)&pu,  g_u);
    cudaGetSymbolAddress((void**)&pm,  g_mid);
    cudaGetSymbolAddress((void**)&pqf, g_qf);
    cudaGetSymbolAddress((void**)&pkf, g_kf);
    cudaGetSymbolAddress((void**)&pbq, g_bqkv);
    cudaGetSymbolAddress((void**)&pq2, g_q2);
    cudaGetSymbolAddress((void**)&pk2, g_k2);
    cudaGetSymbolAddress((void**)&plm, g_lm1);
    cudaGetSymbolAddress((void**)&plh, g_lvh);
    cudaGetSymbolAddress((void**)&pll, g_lvl);
    cudaGetSymbolAddress((void**)&pahi, g_ahi);
    cudaGetSymbolAddress((void**)&palo, g_alo);
    cudaGetSymbolAddress((void**)&pwhi, g_Whi);
    cudaGetSymbolAddress((void**)&pwlo, g_Wlo);

    cudaFuncSetAttribute((const void*)k_gemm_mma,
                         cudaFuncAttributeMaxDynamicSharedMemorySize, GEMM_SMEM);
    cudaFuncSetAttribute((const void*)k_gemm_mma,
                         cudaFuncAttributePreferredSharedMemoryCarveout, 100);
    cudaFuncSetAttribute((const void*)k_attn3,
                         cudaFuncAttributeMaxDynamicSharedMemorySize, ATT2_SMEM);
    cudaFuncSetAttribute((const void*)k_attn3,
                         cudaFuncAttributePreferredSharedMemoryCarveout, 100);

    double betaD  = std::exp(std::lgamma(Dn / 2.0)  + std::lgamma(0.5) - std::lgamma(Dn / 2.0 + 0.5));
    double betaHD = std::exp(std::lgamma(HDn / 2.0) + std::lgamma(0.5) - std::lgamma(HDn / 2.0 + 0.5));
    float ratio_split = (float)(betaHD / betaD);
    float ratio_cat   = (float)(betaD / betaHD);

    constexpr int DD = Dn * Dn, FD = FFn * Dn;
    WCvtArgs wa;
    int idx = 0;
    auto add = [&](const float* s, long long off, int n) {
        wa.src[idx] = s; wa.off[idx] = off; wa.n4[idx] = n / 4; idx++;
    };
    for (int l = 0; l < Ln; l++) {
        long long base = l * WLL;
        add(Wq + (size_t)l * DD, base,               DD);
        add(Wk + (size_t)l * DD, base + DD,          DD);
        add(Wv + (size_t)l * DD, base + 2 * DD,      DD);
        add(Wo + (size_t)l * DD, base + 3 * DD,      DD);
        add(W1 + (size_t)l * FD, base + 4 * DD,      FD);
        add(W2 + (size_t)l * FD, base + 4 * DD + FD, FD);
    }
    add(Wout, 4 * WLL, DD);
    k_wcvt<<<dim3(1024, 25), 256>>>(wa, pwhi, pwlo);
    k_bfill<<<dim3(6, Ln), 256>>>(bq, bk, bv, pbq);

    auto gemm = [&](long long woff, const float* bias, float* Cout, int Ni, int Ki) {
        k_gemm_mma<<<dim3(Ni / 64, Mn / 64), 256, GEMM_SMEM>>>(
            pahi, palo, pwhi + woff, pwlo + woff, bias, Cout, Ni, Ki);
    };

    k_mobius_add<128><<<Mn, 128>>>(x, pos, px, Sn);

    for (int l = 0; l < Ln; l++) {
        long long base = l * WLL;
        // ---- attention ----
        if (l == 0)
            k_pln2bf<<<Mn, 128>>>(px, ln1w, ln1b, pahi, palo);
        gemm(base, pbq + l * 3 * Dn, pu, 3 * Dn, Dn);   // fused QKV
        k_post_qkv3<<<dim3(Mn, 3), 128>>>(pu, pqf, pkf, plh, pll,
                                          pq2, pk2, plm, ratio_split);
        k_attn3<<<dim3(Sn / 128, BHn), 256, ATT2_SMEM>>>(
            pqf, pkf, plh, pll, pq2, pk2, plm, tau, gam, l, pm);

        k_concat2bf<<<Mn, 128>>>(pm, pahi, palo, ratio_cat);
        gemm(base + 3 * DD, bo + l * Dn, pu, Dn, Dn);
        k_expmadd_pln<<<Mn, 128>>>(pu, px, ln2w + l * Dn, ln2b + l * Dn, pahi, palo);

        // ---- FFN ----
        gemm(base + 4 * DD, b1 + l * FFn, pu, FFn, Dn);
        k_ffnmid2bf<<<Mn, 256>>>(pu, pahi, palo);
        gemm(base + 4 * DD + FD, b2 + l * Dn, pu, Dn, FFn);
        if (l < Ln - 1) {
            k_expmadd_pln<<<Mn, 128>>>(pu, px, ln1w + (l + 1) * Dn, ln1b + (l + 1) * Dn,
                                       pahi, palo);
        } else {
            k_expmadd_log2bf<<<Mn, 128>>>(pu, px, pahi, palo);
        }
    }

    // ---- head ----
    gemm(4 * WLL, bout, pu, Dn, Dn);
    k_expmap_out<<<Mn, 128>>>(pu, outp);
}